// round 16
// baseline (speedup 1.0000x reference)
#include <cuda_runtime.h>
#include <cuda_fp16.h>
#include <cstdint>
#include <cstddef>

using fp16 = __half;

constexpr int Bv = 4, Tv = 2048, Cv = 1024, Hn = 16, Dv = 64;
constexpr int Mv = Bv * Tv;   // 8192

// exp(S/8) == exp2(S * 0.125 * log2(e)); scale folded into Q projection.
constexpr float QSCALE = 0.18033688011112042f;   // 0.125 * log2(e)

// ---------------------------------------------------------------------------
// Scratch (device globals)
// ---------------------------------------------------------------------------
__device__ fp16 g_xh[(size_t)Mv * Cv];
__device__ fp16 g_wh[(size_t)4 * Cv * Cv];
__device__ fp16 g_qh[(size_t)Mv * Cv];
__device__ fp16 g_kh[(size_t)Mv * Cv];
__device__ fp16 g_vh[(size_t)Mv * Cv];
__device__ fp16 g_yh[(size_t)Mv * Cv], g_yl[(size_t)Mv * Cv];

// ---------------------------------------------------------------------------
// Helpers
// ---------------------------------------------------------------------------
__device__ __forceinline__ uint32_t smem_u32(const void* p) {
    uint32_t a;
    asm("{ .reg .u64 t; cvta.to.shared.u64 t, %1; cvt.u32.u64 %0, t; }" : "=r"(a) : "l"(p));
    return a;
}
#define CP16(dst, src) \
    asm volatile("cp.async.cg.shared.global [%0], [%1], 16;" \
                 :: "r"(dst), "l"(__cvta_generic_to_global(src)) : "memory")
#define CPC() asm volatile("cp.async.commit_group;" ::: "memory")
#define CPW(n) asm volatile("cp.async.wait_group %0;" :: "n"(n) : "memory")

__device__ __forceinline__ void ldsm4(uint32_t r[4], uint32_t a) {
    asm volatile("ldmatrix.sync.aligned.m8n8.x4.shared.b16 {%0,%1,%2,%3}, [%4];"
                 : "=r"(r[0]), "=r"(r[1]), "=r"(r[2]), "=r"(r[3]) : "r"(a));
}
__device__ __forceinline__ void ldsm4t(uint32_t r[4], uint32_t a) {
    asm volatile("ldmatrix.sync.aligned.m8n8.x4.trans.shared.b16 {%0,%1,%2,%3}, [%4];"
                 : "=r"(r[0]), "=r"(r[1]), "=r"(r[2]), "=r"(r[3]) : "r"(a));
}
__device__ __forceinline__ void mma_f16(float c[4], const uint32_t a[4],
                                        uint32_t b0, uint32_t b1) {
    asm volatile("mma.sync.aligned.m16n8k16.row.col.f32.f16.f16.f32 "
                 "{%0,%1,%2,%3}, {%4,%5,%6,%7}, {%8,%9}, {%0,%1,%2,%3};"
                 : "+f"(c[0]), "+f"(c[1]), "+f"(c[2]), "+f"(c[3])
                 : "r"(a[0]), "r"(a[1]), "r"(a[2]), "r"(a[3]), "r"(b0), "r"(b1));
}
__device__ __forceinline__ uint32_t f22h(float a, float b) {
    __half2 h = __floats2half2_rn(a, b);
    return *reinterpret_cast<uint32_t*>(&h);
}
// packed fp16 exp2: one MUFU op for two values
__device__ __forceinline__ uint32_t ex2_h2(uint32_t x) {
    uint32_t y;
    asm("ex2.approx.f16x2 %0, %1;" : "=r"(y) : "r"(x));
    return y;
}
__device__ __forceinline__ void split_pack(float v0, float v1, uint32_t& hi, uint32_t& lo) {
    fp16 h0 = __float2half_rn(v0), h1 = __float2half_rn(v1);
    fp16 l0 = __float2half_rn(v0 - __half2float(h0));
    fp16 l1 = __float2half_rn(v1 - __half2float(h1));
    hi = f22h(__half2float(h0), __half2float(h1));
    lo = f22h(__half2float(l0), __half2float(l1));
}

// ---------------------------------------------------------------------------
// converts
// ---------------------------------------------------------------------------
__global__ __launch_bounds__(256) void cvt_kernel(
    const float* __restrict__ in, fp16* __restrict__ out, int n4)
{
    const int i = blockIdx.x * blockDim.x + threadIdx.x;
    if (i >= n4) return;
    float4 v = reinterpret_cast<const float4*>(in)[i];
    reinterpret_cast<uint2*>(out)[i] = make_uint2(f22h(v.x, v.y), f22h(v.z, v.w));
}

__global__ __launch_bounds__(256) void cvt4_kernel(
    const float* __restrict__ s0, const float* __restrict__ s1,
    const float* __restrict__ s2, const float* __restrict__ s3,
    fp16* __restrict__ dst, int n4)
{
    const int i = blockIdx.x * blockDim.x + threadIdx.x;
    if (i >= n4) return;
    const float* s = (blockIdx.y == 0) ? s0 : (blockIdx.y == 1) ? s1
                   : (blockIdx.y == 2) ? s2 : s3;
    fp16* d = dst + (size_t)blockIdx.y * (size_t)Cv * Cv;
    float4 v = reinterpret_cast<const float4*>(s)[i];
    reinterpret_cast<uint2*>(d)[i] = make_uint2(f22h(v.x, v.y), f22h(v.z, v.w));
}

// ---------------------------------------------------------------------------
// mma GEMM (templated): out[M,N] = (Ah[+Al])[M,K] @ Bh[N,K]^T + bias
// CTA 128x128, kblock 64, 8 warps (4x2), warp tile 32x64. (unchanged)
// ---------------------------------------------------------------------------
constexpr int GK = 64;
constexpr int GSTR = 72;                      // fp16 row stride (144 B)
constexpr int GT_BYTES = 128 * GSTR * 2;      // 18432
constexpr int NKB = Cv / GK;                  // 16
constexpr int GEMM_SMEM = 6 * GT_BYTES;       // 110592

template <int NTERMS, int MODE>
__global__ __launch_bounds__(256, 2) void mma_gemm(
    const fp16* __restrict__ Ah, const fp16* __restrict__ Al,
    const fp16* __restrict__ Wbase,
    const float* __restrict__ b0, const float* __restrict__ b1,
    const float* __restrict__ b2,
    float* __restrict__ out32,
    fp16* __restrict__ o0, fp16* __restrict__ o1, fp16* __restrict__ o2)
{
    constexpr int STAGE = (NTERMS + 1) * GT_BYTES;
    constexpr int S = (NTERMS == 1) ? 3 : 2;

    extern __shared__ char smem[];
    const uint32_t sbb = smem_u32(smem);
    const int tid = threadIdx.x, lane = tid & 31, wid = tid >> 5;
    const int wm = wid & 3, wn = wid >> 2;
    const int m0 = blockIdx.y * 128;
    const int n0g = blockIdx.x * 128;
    const int wsel = (MODE == 2) ? (n0g >> 10) : 0;
    const int n0 = n0g & 1023;

    const fp16* __restrict__ Bh = Wbase + (size_t)wsel * Cv * Cv;
    const float* __restrict__ bias = (MODE == 2)
        ? ((wsel == 0) ? b0 : (wsel == 1) ? b1 : b2) : b0;
    fp16* __restrict__ oh = (wsel == 0) ? o0 : (wsel == 1) ? o1 : o2;

    auto g2s = [&](int stage, int kb) {
        const uint32_t st = sbb + stage * STAGE;
        const int k0 = kb * GK;
        #pragma unroll
        for (int t = 0; t < NTERMS + 1; t++) {
            const fp16* src = (t == 0) ? Ah : (t == 1 && NTERMS == 2) ? Al : Bh;
            const int row0 = (t == NTERMS) ? n0 : m0;
            const uint32_t tb = st + t * GT_BYTES;
            #pragma unroll
            for (int j = 0; j < 4; j++) {
                const int idx = tid + j * 256;
                const int r = idx >> 3, c = (idx & 7) * 8;
                CP16(tb + (uint32_t)((r * GSTR + c) * 2),
                     src + (size_t)(row0 + r) * Cv + k0 + c);
            }
        }
    };
    auto fad = [&](uint32_t tb, int rb, int cb) -> uint32_t {
        const int r = rb + (lane & 7) + 8 * ((lane >> 3) & 1);
        const int c = cb + 8 * (lane >> 4);
        return tb + (uint32_t)((r * GSTR + c) * 2);
    };

    float acc[2][8][4] = {};

    #pragma unroll
    for (int s = 0; s < S - 1; s++) { g2s(s, s); CPC(); }

    for (int kb = 0; kb < NKB; kb++) {
        CPW(S - 2);
        __syncthreads();
        if (kb + S - 1 < NKB) g2s((kb + S - 1) % S, kb + S - 1);
        CPC();

        const uint32_t st = sbb + (kb % S) * STAGE;
        #pragma unroll
        for (int ks = 0; ks < 4; ks++) {
            uint32_t ah[2][4], al[2][4], bh4[4][4];
            #pragma unroll
            for (int mt = 0; mt < 2; mt++) {
                ldsm4(ah[mt], fad(st + 0 * GT_BYTES, wm * 32 + mt * 16, ks * 16));
                if (NTERMS == 2)
                    ldsm4(al[mt], fad(st + 1 * GT_BYTES, wm * 32 + mt * 16, ks * 16));
            }
            #pragma unroll
            for (int g = 0; g < 4; g++)
                ldsm4(bh4[g], fad(st + NTERMS * GT_BYTES, wn * 64 + g * 16, ks * 16));
            #pragma unroll
            for (int nt = 0; nt < 8; nt++) {
                const int g = nt >> 1, o = nt & 1;
                const uint32_t bb0 = bh4[g][o], bb1 = bh4[g][o + 2];
                #pragma unroll
                for (int mt = 0; mt < 2; mt++) {
                    mma_f16(acc[mt][nt], ah[mt], bb0, bb1);
                    if (NTERMS == 2)
                        mma_f16(acc[mt][nt], al[mt], bb0, bb1);
                }
            }
        }
    }

    // epilogue
    const float osc = (MODE == 2 && wsel == 0) ? QSCALE : 1.0f;
    #pragma unroll
    for (int mt = 0; mt < 2; mt++) {
        const int mr = m0 + wm * 32 + mt * 16 + (lane >> 2);
        #pragma unroll
        for (int half = 0; half < 2; half++) {
            const int m = mr + half * 8;
            const int bb = m >> 11, t = m & (Tv - 1);
            #pragma unroll
            for (int nt = 0; nt < 8; nt++) {
                const int n = n0 + wn * 64 + nt * 8 + (lane & 3) * 2;
                const float v0 = (acc[mt][nt][half * 2 + 0] + bias[n]) * osc;
                const float v1 = (acc[mt][nt][half * 2 + 1] + bias[n + 1]) * osc;
                if (MODE == 0) {
                    *reinterpret_cast<float2*>(out32 + (size_t)m * Cv + n) = make_float2(v0, v1);
                } else {
                    const int h = n >> 6, d = n & 63;
                    const size_t o = (((size_t)(bb * Hn + h)) * Tv + t) * Dv + d;
                    *reinterpret_cast<uint32_t*>(oh + o) = f22h(v0, v1);
                }
            }
        }
    }
}

// ---------------------------------------------------------------------------
// mma attention: per (b,h), 128 q rows/CTA, 8 warps, 64-row K/V stages,
// 3-stage pipeline, 3 CTAs/SM. P computed with ex2.approx.f16x2 (halves
// MUFU ops vs f32 ex2); row sums recovered from the packed fp16 P, so the
// normalization P/rs is self-consistent.
// ---------------------------------------------------------------------------
constexpr int VSTR = 72;                     // fp16 stride (144 B rows)
constexpr int QT_BYTES = 128 * VSTR * 2;     // 18432
constexpr int KT_BYTES = 64 * VSTR * 2;      // 9216
constexpr int ASTAGE = 2 * KT_BYTES;         // 18432
constexpr int AS_N = 3;                      // stages
constexpr int ATT_SMEM = QT_BYTES + AS_N * ASTAGE;   // 73728 -> 3 CTAs/SM
constexpr int NBLK = Tv / 64;                // 32

__global__ __launch_bounds__(256, 3) void mma_attn()
{
    extern __shared__ char smem[];
    const uint32_t sbb = smem_u32(smem);
    const int tid = threadIdx.x, lane = tid & 31, wid = tid >> 5;
    const int bh = blockIdx.y, q0 = blockIdx.x * 128;

    const fp16* qh = g_qh + (size_t)bh * Tv * Dv;
    const fp16* kh = g_kh + (size_t)bh * Tv * Dv;
    const fp16* vh = g_vh + (size_t)bh * Tv * Dv;

    const uint32_t QH = sbb, ST0 = sbb + QT_BYTES;

    auto g2s = [&](int stage, int blk) {
        const uint32_t st = ST0 + stage * ASTAGE;
        const int s0 = blk * 64;
        #pragma unroll
        for (int j = 0; j < 4; j++) {
            const int idx = tid + j * 256;          // 0..1023
            const int r = (idx >> 3) & 63;
            const int dc = (idx & 7) * 8;
            const uint32_t so = (uint32_t)((r * VSTR + dc) * 2);
            if (idx < 512) CP16(st + so,            kh + (size_t)(s0 + r) * Dv + dc);
            else           CP16(st + KT_BYTES + so, vh + (size_t)(s0 + r) * Dv + dc);
        }
    };
    auto fad = [&](uint32_t tb, int rb, int cb) -> uint32_t {
        const int r = rb + (lane & 7) + 8 * ((lane >> 3) & 1);
        const int c = cb + 8 * (lane >> 4);
        return tb + (uint32_t)((r * VSTR + c) * 2);
    };

    // prologue: Q + stage0 in one group, then stage1
    #pragma unroll
    for (int j = 0; j < 4; j++) {
        const int idx = tid + j * 256;
        const int r = idx >> 3, dc = (idx & 7) * 8;
        CP16(QH + (uint32_t)((r * VSTR + dc) * 2), qh + (size_t)(q0 + r) * Dv + dc);
    }
    g2s(0, 0); CPC();
    g2s(1, 1); CPC();

    CPW(1); __syncthreads();
    uint32_t qfh[4][4];
    #pragma unroll
    for (int ks = 0; ks < 4; ks++)
        ldsm4(qfh[ks], fad(QH, wid * 16, ks * 16));

    float oacc[8][4] = {};
    float rs0 = 0.f, rs1 = 0.f;

    for (int blk = 0; blk < NBLK; blk++) {
        CPW(1);
        __syncthreads();
        if (blk + 2 < NBLK) g2s((blk + 2) % AS_N, blk + 2);
        CPC();

        const uint32_t st = ST0 + (blk % AS_N) * ASTAGE;

        // S = Qs Kh^T (Q carries the softmax scale, log2 domain)
        float sacc[8][4] = {};
        #pragma unroll
        for (int ks = 0; ks < 4; ks++) {
            uint32_t kf[4][4];
            #pragma unroll
            for (int g = 0; g < 4; g++)
                ldsm4(kf[g], fad(st, g * 16, ks * 16));
            #pragma unroll
            for (int nt = 0; nt < 8; nt++) {
                const int g = nt >> 1, o = nt & 1;
                mma_f16(sacc[nt], qfh[ks], kf[g][o], kf[g][o + 2]);
            }
        }

        // P = ex2(S) in packed fp16 (one MUFU per pair); rs from the same
        // fp16 P values so normalization is self-consistent.
        uint32_t pah[4][4];
        #pragma unroll
        for (int nt = 0; nt < 8; nt++) {
            const uint32_t p01 = ex2_h2(f22h(sacc[nt][0], sacc[nt][1]));
            const uint32_t p23 = ex2_h2(f22h(sacc[nt][2], sacc[nt][3]));
            const __half2 h01 = *reinterpret_cast<const __half2*>(&p01);
            const __half2 h23 = *reinterpret_cast<const __half2*>(&p23);
            rs0 += __low2float(h01) + __high2float(h01);
            rs1 += __low2float(h23) + __high2float(h23);
            const int jj = nt >> 1, off = (nt & 1) * 2;
            pah[jj][off]     = p01;
            pah[jj][off + 1] = p23;
        }

        // O += Ph Vh
        #pragma unroll
        for (int ks = 0; ks < 4; ks++) {
            uint32_t vf[4][4];
            #pragma unroll
            for (int g = 0; g < 4; g++)
                ldsm4t(vf[g], fad(st + KT_BYTES, ks * 16, g * 16));
            #pragma unroll
            for (int dt = 0; dt < 8; dt++) {
                const int g = dt >> 1, o = (dt & 1) * 2;
                mma_f16(oacc[dt], pah[ks], vf[g][o], vf[g][o + 1]);
            }
        }
    }

    rs0 += __shfl_xor_sync(0xffffffffu, rs0, 1);
    rs0 += __shfl_xor_sync(0xffffffffu, rs0, 2);
    rs1 += __shfl_xor_sync(0xffffffffu, rs1, 1);
    rs1 += __shfl_xor_sync(0xffffffffu, rs1, 2);
    const float inv0 = 1.0f / rs0, inv1 = 1.0f / rs1;

    const int b = bh >> 4, h = bh & 15;
    const int t0 = q0 + wid * 16 + (lane >> 2);
    #pragma unroll
    for (int dt = 0; dt < 8; dt++) {
        const int col = h * 64 + dt * 8 + (lane & 3) * 2;
        uint32_t hi, lo;
        split_pack(oacc[dt][0] * inv0, oacc[dt][1] * inv0, hi, lo);
        size_t o = (size_t)(b * Tv + t0) * Cv + col;
        *reinterpret_cast<uint32_t*>(g_yh + o) = hi;
        *reinterpret_cast<uint32_t*>(g_yl + o) = lo;
        split_pack(oacc[dt][2] * inv1, oacc[dt][3] * inv1, hi, lo);
        o = (size_t)(b * Tv + t0 + 8) * Cv + col;
        *reinterpret_cast<uint32_t*>(g_yh + o) = hi;
        *reinterpret_cast<uint32_t*>(g_yl + o) = lo;
    }
}

// ---------------------------------------------------------------------------
extern "C" void kernel_launch(void* const* d_in, const int* in_sizes, int n_in,
                              void* d_out, int out_size)
{
    const float* x  = (const float*)d_in[0];
    const float* Wq = (const float*)d_in[1];
    const float* bq = (const float*)d_in[2];
    const float* Wk = (const float*)d_in[3];
    const float* bk = (const float*)d_in[4];
    const float* Wv = (const float*)d_in[5];
    const float* bv = (const float*)d_in[6];
    const float* Wp = (const float*)d_in[7];
    const float* bp = (const float*)d_in[8];
    float* out = (float*)d_out;

    fp16 *xh, *wh, *qh, *kh, *vh, *yh, *yl;
    cudaGetSymbolAddress((void**)&xh, g_xh);
    cudaGetSymbolAddress((void**)&wh, g_wh);
    cudaGetSymbolAddress((void**)&qh, g_qh);
    cudaGetSymbolAddress((void**)&kh, g_kh);
    cudaGetSymbolAddress((void**)&vh, g_vh);
    cudaGetSymbolAddress((void**)&yh, g_yh);
    cudaGetSymbolAddress((void**)&yl, g_yl);

    cudaFuncSetAttribute(mma_gemm<1, 2>, cudaFuncAttributeMaxDynamicSharedMemorySize, GEMM_SMEM);
    cudaFuncSetAttribute(mma_gemm<2, 0>, cudaFuncAttributeMaxDynamicSharedMemorySize, GEMM_SMEM);
    cudaFuncSetAttribute(mma_attn, cudaFuncAttributeMaxDynamicSharedMemorySize, ATT_SMEM);

    const size_t WN = (size_t)Cv * Cv;
    const int xs4 = Mv * Cv / 4, ws4 = (int)(WN / 4);

    cvt_kernel<<<(xs4 + 255) / 256, 256>>>(x, xh, xs4);
    {
        dim3 cg((ws4 + 255) / 256, 4);
        cvt4_kernel<<<cg, 256>>>(Wq, Wk, Wv, Wp, wh, ws4);
    }

    dim3 qkvGrid(24, Mv / 128);
    mma_gemm<1, 2><<<qkvGrid, 256, GEMM_SMEM>>>(
        xh, nullptr, wh, bq, bk, bv, nullptr, qh, kh, vh);

    dim3 aGrid(Tv / 128, Bv * Hn);
    mma_attn<<<aGrid, 256, ATT_SMEM>>>();

    dim3 pGrid(8, Mv / 128);
    mma_gemm<2, 0><<<pGrid, 256, GEMM_SMEM>>>(
        yh, yl, wh + 3 * WN, bp, bp, bp, out, nullptr, nullptr, nullptr);
}

// round 17
// speedup vs baseline: 1.1224x; 1.1224x over previous
#include <cuda_runtime.h>
#include <cuda_fp16.h>
#include <cstdint>
#include <cstddef>

using fp16 = __half;

constexpr int Bv = 4, Tv = 2048, Cv = 1024, Hn = 16, Dv = 64;
constexpr int Mv = Bv * Tv;   // 8192

// exp(S/8) == exp2(S * 0.125 * log2(e)); scale folded into Q projection.
constexpr float QSCALE = 0.18033688011112042f;   // 0.125 * log2(e)

// ---------------------------------------------------------------------------
// Scratch (device globals)
// ---------------------------------------------------------------------------
__device__ fp16 g_xh[(size_t)Mv * Cv];
__device__ fp16 g_wh[(size_t)4 * Cv * Cv];
__device__ fp16 g_qh[(size_t)Mv * Cv];
__device__ fp16 g_kh[(size_t)Mv * Cv];
__device__ fp16 g_vh[(size_t)Mv * Cv];
__device__ fp16 g_yh[(size_t)Mv * Cv];

// ---------------------------------------------------------------------------
// Helpers
// ---------------------------------------------------------------------------
__device__ __forceinline__ uint32_t smem_u32(const void* p) {
    uint32_t a;
    asm("{ .reg .u64 t; cvta.to.shared.u64 t, %1; cvt.u32.u64 %0, t; }" : "=r"(a) : "l"(p));
    return a;
}
#define CP16(dst, src) \
    asm volatile("cp.async.cg.shared.global [%0], [%1], 16;" \
                 :: "r"(dst), "l"(__cvta_generic_to_global(src)) : "memory")
#define CPC() asm volatile("cp.async.commit_group;" ::: "memory")
#define CPW(n) asm volatile("cp.async.wait_group %0;" :: "n"(n) : "memory")

__device__ __forceinline__ void ldsm4(uint32_t r[4], uint32_t a) {
    asm volatile("ldmatrix.sync.aligned.m8n8.x4.shared.b16 {%0,%1,%2,%3}, [%4];"
                 : "=r"(r[0]), "=r"(r[1]), "=r"(r[2]), "=r"(r[3]) : "r"(a));
}
__device__ __forceinline__ void ldsm4t(uint32_t r[4], uint32_t a) {
    asm volatile("ldmatrix.sync.aligned.m8n8.x4.trans.shared.b16 {%0,%1,%2,%3}, [%4];"
                 : "=r"(r[0]), "=r"(r[1]), "=r"(r[2]), "=r"(r[3]) : "r"(a));
}
__device__ __forceinline__ void mma_f16(float c[4], const uint32_t a[4],
                                        uint32_t b0, uint32_t b1) {
    asm volatile("mma.sync.aligned.m16n8k16.row.col.f32.f16.f16.f32 "
                 "{%0,%1,%2,%3}, {%4,%5,%6,%7}, {%8,%9}, {%0,%1,%2,%3};"
                 : "+f"(c[0]), "+f"(c[1]), "+f"(c[2]), "+f"(c[3])
                 : "r"(a[0]), "r"(a[1]), "r"(a[2]), "r"(a[3]), "r"(b0), "r"(b1));
}
__device__ __forceinline__ uint32_t f22h(float a, float b) {
    __half2 h = __floats2half2_rn(a, b);
    return *reinterpret_cast<uint32_t*>(&h);
}
__device__ __forceinline__ float ex2(float x) {
    float y;
    asm("ex2.approx.f32 %0, %1;" : "=f"(y) : "f"(x));
    return y;
}

// ---------------------------------------------------------------------------
// converts
// ---------------------------------------------------------------------------
__global__ __launch_bounds__(256) void cvt_kernel(
    const float* __restrict__ in, fp16* __restrict__ out, int n4)
{
    const int i = blockIdx.x * blockDim.x + threadIdx.x;
    if (i >= n4) return;
    float4 v = reinterpret_cast<const float4*>(in)[i];
    reinterpret_cast<uint2*>(out)[i] = make_uint2(f22h(v.x, v.y), f22h(v.z, v.w));
}

__global__ __launch_bounds__(256) void cvt4_kernel(
    const float* __restrict__ s0, const float* __restrict__ s1,
    const float* __restrict__ s2, const float* __restrict__ s3,
    fp16* __restrict__ dst, int n4)
{
    const int i = blockIdx.x * blockDim.x + threadIdx.x;
    if (i >= n4) return;
    const float* s = (blockIdx.y == 0) ? s0 : (blockIdx.y == 1) ? s1
                   : (blockIdx.y == 2) ? s2 : s3;
    fp16* d = dst + (size_t)blockIdx.y * (size_t)Cv * Cv;
    float4 v = reinterpret_cast<const float4*>(s)[i];
    reinterpret_cast<uint2*>(d)[i] = make_uint2(f22h(v.x, v.y), f22h(v.z, v.w));
}

// ---------------------------------------------------------------------------
// mma GEMM (templated): out[M,N] = Ah[M,K] @ Bh[N,K]^T + bias   (1-term now
// everywhere; NTERMS kept for flexibility)
// CTA 128x128, kblock 64, 8 warps (4x2), warp tile 32x64.
// ---------------------------------------------------------------------------
constexpr int GK = 64;
constexpr int GSTR = 72;                      // fp16 row stride (144 B)
constexpr int GT_BYTES = 128 * GSTR * 2;      // 18432
constexpr int NKB = Cv / GK;                  // 16
constexpr int GEMM_SMEM = 6 * GT_BYTES;       // 110592

template <int NTERMS, int MODE>
__global__ __launch_bounds__(256, 2) void mma_gemm(
    const fp16* __restrict__ Ah, const fp16* __restrict__ Al,
    const fp16* __restrict__ Wbase,
    const float* __restrict__ b0, const float* __restrict__ b1,
    const float* __restrict__ b2,
    float* __restrict__ out32,
    fp16* __restrict__ o0, fp16* __restrict__ o1, fp16* __restrict__ o2)
{
    constexpr int STAGE = (NTERMS + 1) * GT_BYTES;
    constexpr int S = (NTERMS == 1) ? 3 : 2;

    extern __shared__ char smem[];
    const uint32_t sbb = smem_u32(smem);
    const int tid = threadIdx.x, lane = tid & 31, wid = tid >> 5;
    const int wm = wid & 3, wn = wid >> 2;
    const int m0 = blockIdx.y * 128;
    const int n0g = blockIdx.x * 128;
    const int wsel = (MODE == 2) ? (n0g >> 10) : 0;
    const int n0 = n0g & 1023;

    const fp16* __restrict__ Bh = Wbase + (size_t)wsel * Cv * Cv;
    const float* __restrict__ bias = (MODE == 2)
        ? ((wsel == 0) ? b0 : (wsel == 1) ? b1 : b2) : b0;
    fp16* __restrict__ oh = (wsel == 0) ? o0 : (wsel == 1) ? o1 : o2;

    auto g2s = [&](int stage, int kb) {
        const uint32_t st = sbb + stage * STAGE;
        const int k0 = kb * GK;
        #pragma unroll
        for (int t = 0; t < NTERMS + 1; t++) {
            const fp16* src = (t == 0) ? Ah : (t == 1 && NTERMS == 2) ? Al : Bh;
            const int row0 = (t == NTERMS) ? n0 : m0;
            const uint32_t tb = st + t * GT_BYTES;
            #pragma unroll
            for (int j = 0; j < 4; j++) {
                const int idx = tid + j * 256;
                const int r = idx >> 3, c = (idx & 7) * 8;
                CP16(tb + (uint32_t)((r * GSTR + c) * 2),
                     src + (size_t)(row0 + r) * Cv + k0 + c);
            }
        }
    };
    auto fad = [&](uint32_t tb, int rb, int cb) -> uint32_t {
        const int r = rb + (lane & 7) + 8 * ((lane >> 3) & 1);
        const int c = cb + 8 * (lane >> 4);
        return tb + (uint32_t)((r * GSTR + c) * 2);
    };

    float acc[2][8][4] = {};

    #pragma unroll
    for (int s = 0; s < S - 1; s++) { g2s(s, s); CPC(); }

    for (int kb = 0; kb < NKB; kb++) {
        CPW(S - 2);
        __syncthreads();
        if (kb + S - 1 < NKB) g2s((kb + S - 1) % S, kb + S - 1);
        CPC();

        const uint32_t st = sbb + (kb % S) * STAGE;
        #pragma unroll
        for (int ks = 0; ks < 4; ks++) {
            uint32_t ah[2][4], al[2][4], bh4[4][4];
            #pragma unroll
            for (int mt = 0; mt < 2; mt++) {
                ldsm4(ah[mt], fad(st + 0 * GT_BYTES, wm * 32 + mt * 16, ks * 16));
                if (NTERMS == 2)
                    ldsm4(al[mt], fad(st + 1 * GT_BYTES, wm * 32 + mt * 16, ks * 16));
            }
            #pragma unroll
            for (int g = 0; g < 4; g++)
                ldsm4(bh4[g], fad(st + NTERMS * GT_BYTES, wn * 64 + g * 16, ks * 16));
            #pragma unroll
            for (int nt = 0; nt < 8; nt++) {
                const int g = nt >> 1, o = nt & 1;
                const uint32_t bb0 = bh4[g][o], bb1 = bh4[g][o + 2];
                #pragma unroll
                for (int mt = 0; mt < 2; mt++) {
                    mma_f16(acc[mt][nt], ah[mt], bb0, bb1);
                    if (NTERMS == 2)
                        mma_f16(acc[mt][nt], al[mt], bb0, bb1);
                }
            }
        }
    }

    // epilogue
    const float osc = (MODE == 2 && wsel == 0) ? QSCALE : 1.0f;
    #pragma unroll
    for (int mt = 0; mt < 2; mt++) {
        const int mr = m0 + wm * 32 + mt * 16 + (lane >> 2);
        #pragma unroll
        for (int half = 0; half < 2; half++) {
            const int m = mr + half * 8;
            const int bb = m >> 11, t = m & (Tv - 1);
            #pragma unroll
            for (int nt = 0; nt < 8; nt++) {
                const int n = n0 + wn * 64 + nt * 8 + (lane & 3) * 2;
                const float v0 = (acc[mt][nt][half * 2 + 0] + bias[n]) * osc;
                const float v1 = (acc[mt][nt][half * 2 + 1] + bias[n + 1]) * osc;
                if (MODE == 0) {
                    *reinterpret_cast<float2*>(out32 + (size_t)m * Cv + n) = make_float2(v0, v1);
                } else {
                    const int h = n >> 6, d = n & 63;
                    const size_t o = (((size_t)(bb * Hn + h)) * Tv + t) * Dv + d;
                    *reinterpret_cast<uint32_t*>(oh + o) = f22h(v0, v1);
                }
            }
        }
    }
}

// ---------------------------------------------------------------------------
// mma attention (R15 version — f32 ex2, proven 211us): per (b,h), 128 q
// rows/CTA, 8 warps, 64-row K/V stages, 3-stage pipeline, 3 CTAs/SM.
// Epilogue writes yh only (proj is 1-term now).
// ---------------------------------------------------------------------------
constexpr int VSTR = 72;                     // fp16 stride (144 B rows)
constexpr int QT_BYTES = 128 * VSTR * 2;     // 18432
constexpr int KT_BYTES = 64 * VSTR * 2;      // 9216
constexpr int ASTAGE = 2 * KT_BYTES;         // 18432
constexpr int AS_N = 3;                      // stages
constexpr int ATT_SMEM = QT_BYTES + AS_N * ASTAGE;   // 73728 -> 3 CTAs/SM
constexpr int NBLK = Tv / 64;                // 32

__global__ __launch_bounds__(256, 3) void mma_attn()
{
    extern __shared__ char smem[];
    const uint32_t sbb = smem_u32(smem);
    const int tid = threadIdx.x, lane = tid & 31, wid = tid >> 5;
    const int bh = blockIdx.y, q0 = blockIdx.x * 128;

    const fp16* qh = g_qh + (size_t)bh * Tv * Dv;
    const fp16* kh = g_kh + (size_t)bh * Tv * Dv;
    const fp16* vh = g_vh + (size_t)bh * Tv * Dv;

    const uint32_t QH = sbb, ST0 = sbb + QT_BYTES;

    auto g2s = [&](int stage, int blk) {
        const uint32_t st = ST0 + stage * ASTAGE;
        const int s0 = blk * 64;
        #pragma unroll
        for (int j = 0; j < 4; j++) {
            const int idx = tid + j * 256;          // 0..1023
            const int r = (idx >> 3) & 63;
            const int dc = (idx & 7) * 8;
            const uint32_t so = (uint32_t)((r * VSTR + dc) * 2);
            if (idx < 512) CP16(st + so,            kh + (size_t)(s0 + r) * Dv + dc);
            else           CP16(st + KT_BYTES + so, vh + (size_t)(s0 + r) * Dv + dc);
        }
    };
    auto fad = [&](uint32_t tb, int rb, int cb) -> uint32_t {
        const int r = rb + (lane & 7) + 8 * ((lane >> 3) & 1);
        const int c = cb + 8 * (lane >> 4);
        return tb + (uint32_t)((r * VSTR + c) * 2);
    };

    // prologue: Q + stage0 in one group, then stage1
    #pragma unroll
    for (int j = 0; j < 4; j++) {
        const int idx = tid + j * 256;
        const int r = idx >> 3, dc = (idx & 7) * 8;
        CP16(QH + (uint32_t)((r * VSTR + dc) * 2), qh + (size_t)(q0 + r) * Dv + dc);
    }
    g2s(0, 0); CPC();
    g2s(1, 1); CPC();

    CPW(1); __syncthreads();
    uint32_t qfh[4][4];
    #pragma unroll
    for (int ks = 0; ks < 4; ks++)
        ldsm4(qfh[ks], fad(QH, wid * 16, ks * 16));

    float oacc[8][4] = {};
    float rs0 = 0.f, rs1 = 0.f;

    for (int blk = 0; blk < NBLK; blk++) {
        CPW(1);
        __syncthreads();
        if (blk + 2 < NBLK) g2s((blk + 2) % AS_N, blk + 2);
        CPC();

        const uint32_t st = ST0 + (blk % AS_N) * ASTAGE;

        // S = Qs Kh^T (Q carries the softmax scale, log2 domain)
        float sacc[8][4] = {};
        #pragma unroll
        for (int ks = 0; ks < 4; ks++) {
            uint32_t kf[4][4];
            #pragma unroll
            for (int g = 0; g < 4; g++)
                ldsm4(kf[g], fad(st, g * 16, ks * 16));
            #pragma unroll
            for (int nt = 0; nt < 8; nt++) {
                const int g = nt >> 1, o = nt & 1;
                mma_f16(sacc[nt], qfh[ks], kf[g][o], kf[g][o + 2]);
            }
        }

        // P = ex2(S)
        uint32_t pah[4][4];
        #pragma unroll
        for (int nt = 0; nt < 8; nt++) {
            const float p0 = ex2(sacc[nt][0]);
            const float p1 = ex2(sacc[nt][1]);
            const float p2 = ex2(sacc[nt][2]);
            const float p3 = ex2(sacc[nt][3]);
            rs0 += p0 + p1;
            rs1 += p2 + p3;
            const int jj = nt >> 1, off = (nt & 1) * 2;
            pah[jj][off]     = f22h(p0, p1);
            pah[jj][off + 1] = f22h(p2, p3);
        }

        // O += Ph Vh
        #pragma unroll
        for (int ks = 0; ks < 4; ks++) {
            uint32_t vf[4][4];
            #pragma unroll
            for (int g = 0; g < 4; g++)
                ldsm4t(vf[g], fad(st + KT_BYTES, ks * 16, g * 16));
            #pragma unroll
            for (int dt = 0; dt < 8; dt++) {
                const int g = dt >> 1, o = (dt & 1) * 2;
                mma_f16(oacc[dt], pah[ks], vf[g][o], vf[g][o + 1]);
            }
        }
    }

    rs0 += __shfl_xor_sync(0xffffffffu, rs0, 1);
    rs0 += __shfl_xor_sync(0xffffffffu, rs0, 2);
    rs1 += __shfl_xor_sync(0xffffffffu, rs1, 1);
    rs1 += __shfl_xor_sync(0xffffffffu, rs1, 2);
    const float inv0 = 1.0f / rs0, inv1 = 1.0f / rs1;

    const int b = bh >> 4, h = bh & 15;
    const int t0 = q0 + wid * 16 + (lane >> 2);
    #pragma unroll
    for (int dt = 0; dt < 8; dt++) {
        const int col = h * 64 + dt * 8 + (lane & 3) * 2;
        size_t o = (size_t)(b * Tv + t0) * Cv + col;
        *reinterpret_cast<uint32_t*>(g_yh + o) =
            f22h(oacc[dt][0] * inv0, oacc[dt][1] * inv0);
        o = (size_t)(b * Tv + t0 + 8) * Cv + col;
        *reinterpret_cast<uint32_t*>(g_yh + o) =
            f22h(oacc[dt][2] * inv1, oacc[dt][3] * inv1);
    }
}

// ---------------------------------------------------------------------------
extern "C" void kernel_launch(void* const* d_in, const int* in_sizes, int n_in,
                              void* d_out, int out_size)
{
    const float* x  = (const float*)d_in[0];
    const float* Wq = (const float*)d_in[1];
    const float* bq = (const float*)d_in[2];
    const float* Wk = (const float*)d_in[3];
    const float* bk = (const float*)d_in[4];
    const float* Wv = (const float*)d_in[5];
    const float* bv = (const float*)d_in[6];
    const float* Wp = (const float*)d_in[7];
    const float* bp = (const float*)d_in[8];
    float* out = (float*)d_out;

    fp16 *xh, *wh, *qh, *kh, *vh, *yh;
    cudaGetSymbolAddress((void**)&xh, g_xh);
    cudaGetSymbolAddress((void**)&wh, g_wh);
    cudaGetSymbolAddress((void**)&qh, g_qh);
    cudaGetSymbolAddress((void**)&kh, g_kh);
    cudaGetSymbolAddress((void**)&vh, g_vh);
    cudaGetSymbolAddress((void**)&yh, g_yh);

    cudaFuncSetAttribute(mma_gemm<1, 2>, cudaFuncAttributeMaxDynamicSharedMemorySize, GEMM_SMEM);
    cudaFuncSetAttribute(mma_gemm<1, 0>, cudaFuncAttributeMaxDynamicSharedMemorySize, GEMM_SMEM);
    cudaFuncSetAttribute(mma_attn, cudaFuncAttributeMaxDynamicSharedMemorySize, ATT_SMEM);

    const size_t WN = (size_t)Cv * Cv;
    const int xs4 = Mv * Cv / 4, ws4 = (int)(WN / 4);

    cvt_kernel<<<(xs4 + 255) / 256, 256>>>(x, xh, xs4);
    {
        dim3 cg((ws4 + 255) / 256, 4);
        cvt4_kernel<<<cg, 256>>>(Wq, Wk, Wv, Wp, wh, ws4);
    }

    dim3 qkvGrid(24, Mv / 128);
    mma_gemm<1, 2><<<qkvGrid, 256, GEMM_SMEM>>>(
        xh, nullptr, wh, bq, bk, bv, nullptr, qh, kh, vh);

    dim3 aGrid(Tv / 128, Bv * Hn);
    mma_attn<<<aGrid, 256, ATT_SMEM>>>();

    // output projection: 1-term (y-lo residual is iid across k -> ~4.2e-4
    // incoherent contribution; combined budget ~7.6e-4 < 1e-3)
    dim3 pGrid(8, Mv / 128);
    mma_gemm<1, 0><<<pGrid, 256, GEMM_SMEM>>>(
        yh, nullptr, wh + 3 * WN, bp, bp, bp, out, nullptr, nullptr, nullptr);
}